// round 8
// baseline (speedup 1.0000x reference)
#include <cuda_runtime.h>
#include <cuda_fp16.h>
#include <math.h>

typedef unsigned long long ull;

// ---------------- problem constants ----------------
#define NB       64
#define NNODES   1296        // 16*81
#define NC       43
#define OD       16
#define CO_TIMES_OD 688      // 43*16
#define CO4      172         // 688/4

// packed f32x2 FMA (Blackwell sm_103a): two fp32 MACs per instruction, bit-exact fp32
#define FMA2(a,x,y) asm("fma.rn.f32x2 %0, %1, %2, %0;" : "+l"(a) : "l"(x), "l"(y))

#define CPASYNC16(dst_u32, src_ptr) \
    asm volatile("cp.async.cg.shared.global [%0], [%1], 16;" :: "r"(dst_u32), "l"(src_ptr))
#define CPCOMMIT()  asm volatile("cp.async.commit_group;" ::: "memory")
#define CPWAIT0()   asm volatile("cp.async.wait_group 0;" ::: "memory")

static __device__ __forceinline__ float f2lo(ull v){ return __uint_as_float((unsigned)v); }
static __device__ __forceinline__ float f2hi(ull v){ return __uint_as_float((unsigned)(v>>32)); }
static __device__ __forceinline__ ull pack2(float w){ ull r; asm("mov.b64 %0, {%1, %1};" : "=l"(r) : "f"(w)); return r; }

// ---------------- device scratch ----------------
__device__ float  g_w1t[62208];                    // conv1 weights scalar: [(ci*9+ky)*9+kx][co]
__device__ float  g_w2t[2097152];                  // prim  weights scalar: [k][co]
__device__ __align__(16) float2 g_h2[32 * 256 * 24 * 24];  // conv1 output, batch-paired (bp, bp+32)
__device__ float  g_u[NB * NNODES * 8];            // primary capsules (squashed)
__device__ ull    g_pri[(size_t)NB * NNODES * CO4];// priors, fp16x4 packed (114MB)
__device__ float  g_s[NB * CO_TIMES_OD];
__device__ float  g_caps0[NB * CO_TIMES_OD];       // outputs after iter 0
__device__ float  g_capsum[NB * CO_TIMES_OD];      // outputs0 + outputs1 (= logit carrier)

static __device__ __forceinline__ unsigned h2u(__half2 h){ return *reinterpret_cast<unsigned*>(&h); }
static __device__ __forceinline__ __half2 u2h(unsigned u){ return *reinterpret_cast<__half2*>(&u); }

static __device__ __forceinline__ float4 unpk(ull v) {
    float2 a = __half22float2(u2h((unsigned)v));
    float2 b = __half22float2(u2h((unsigned)(v >> 32)));
    return make_float4(a.x, a.y, b.x, b.y);
}

// ---------------- weight transposes ----------------
__global__ void k_tr1(const float* __restrict__ w) {
    int idx = blockIdx.x * 256 + threadIdx.x;
    if (idx >= 62208) return;
    int co = idx & 255; int r = idx >> 8;      // r = (ci*9+ky)*9+kx, 0..242
    int kx = r % 9; int t = r / 9; int ky = t % 9; int ci = t / 9;
    g_w1t[idx] = w[co * 243 + ci * 81 + ky * 9 + kx];
}
// tiled transpose: w [128 co][16384 k] -> g_w2t [16384 k][128 co]
__global__ __launch_bounds__(256) void k_tr2(const float* __restrict__ w) {
    __shared__ float t[32][33];
    int kb = blockIdx.x * 32;        // k tile (512 tiles)
    int cb = blockIdx.y * 32;        // co tile (4 tiles)
    int tx = threadIdx.x & 31, ty = threadIdx.x >> 5;   // 32 x 8
#pragma unroll
    for (int r = 0; r < 32; r += 8)
        t[ty + r][tx] = w[(size_t)(cb + ty + r) * 16384 + kb + tx];   // coalesced along k
    __syncthreads();
#pragma unroll
    for (int r = 0; r < 32; r += 8)
        g_w2t[(size_t)(kb + ty + r) * 128 + cb + tx] = t[tx][ty + r]; // coalesced along co
}

// ---------------- conv1: batch-paired f32x2, (64,3,32,32) -> paired float2 output ----------------
__global__ __launch_bounds__(256, 2) void k_conv1(const float* __restrict__ x,
                                                  const float* __restrict__ bias) {
    int oy = blockIdx.x, bp = blockIdx.y;
    int b0 = bp, b1 = bp + 32;
    int co = threadIdx.x;
    __shared__ float2 xs[864];           // [3 ci][9 r][32 col], pair (b0,b1)
    for (int idx = co; idx < 864; idx += 256) {
        int ci = idx / 288, rem = idx - ci * 288;
        int r = rem >> 5, col = rem & 31;
        int off = (ci * 32 + oy + r) * 32 + col;
        xs[idx] = make_float2(x[b0 * 3072 + off], x[b1 * 3072 + off]);
    }
    __syncthreads();
    const ull* xsu = (const ull*)xs;
    float bv = bias[co];
#pragma unroll 1
    for (int h = 0; h < 2; h++) {        // two halves of the 24-wide output row
        ull acc[12];
#pragma unroll
        for (int i = 0; i < 12; i++) acc[i] = 0ull;
        for (int ci = 0; ci < 3; ci++) {
#pragma unroll
            for (int ky = 0; ky < 9; ky++) {
                ull in[20];
                const ulonglong2* ip = (const ulonglong2*)(xsu + ci * 288 + ky * 32 + h * 12);
#pragma unroll
                for (int j = 0; j < 10; j++) { ulonglong2 t = ip[j]; in[2*j] = t.x; in[2*j+1] = t.y; }
                const float* wp = &g_w1t[((ci * 9 + ky) * 9) * 256 + co];
                ull w[9];
#pragma unroll
                for (int kx = 0; kx < 9; kx++) w[kx] = pack2(wp[kx * 256]);
#pragma unroll
                for (int kx = 0; kx < 9; kx++)
#pragma unroll
                    for (int ox = 0; ox < 12; ox++)
                        FMA2(acc[ox], in[ox + kx], w[kx]);
            }
        }
        float2* hp = &g_h2[((bp * 256 + co) * 24 + oy) * 24 + h * 12];
#pragma unroll
        for (int ox = 0; ox < 12; ox++)
            hp[ox] = make_float2(fmaxf(f2lo(acc[ox]) + bv, 0.f),
                                 fmaxf(f2hi(acc[ox]) + bv, 0.f));
    }
}

// ---------------- prim conv: cp.async double-buffered + fused squash epilogue ----------------
__global__ __launch_bounds__(256, 2) void k_prim(const float* __restrict__ bias) {
    int oy = blockIdx.x, bp = blockIdx.y;     // grid (9, 32)
    int b0 = bp, b1 = bp + 32;
    int tid = threadIdx.x;
    int kh = tid >> 7;          // K-range half
    int co = tid & 127;
    __shared__ __align__(16) float2 hs[2][3072];
    unsigned sb[2];
    sb[0] = (unsigned)__cvta_generic_to_shared(&hs[0][0]);
    sb[1] = (unsigned)__cvta_generic_to_shared(&hs[1][0]);

    int qc16[6], qr[6], qci[6];
#pragma unroll
    for (int j = 0; j < 6; j++) {
        int q = tid + j * 256;
        qc16[j] = q % 12; int t2 = q / 12;
        qr[j] = t2 & 7; qci[j] = t2 >> 3;
    }

    ull acc[9];
#pragma unroll
    for (int i = 0; i < 9; i++) acc[i] = 0ull;

#pragma unroll
    for (int j = 0; j < 6; j++) {
        const float2* src = &g_h2[((size_t)(bp * 256 + qci[j]) * 24 + 2 * oy + qr[j]) * 24 + qc16[j] * 2];
        unsigned dst = sb[0] + (unsigned)((qci[j] * 192 + qr[j] * 24 + qc16[j] * 2) * 8);
        CPASYNC16(dst, src);
    }
    CPCOMMIT(); CPWAIT0();
    __syncthreads();

#pragma unroll 1
    for (int cc = 0; cc < 16; cc++) {      // 16 chunks of 16 input channels
        if (cc < 15) {
            int nb = (cc + 1) & 1;
#pragma unroll
            for (int j = 0; j < 6; j++) {
                const float2* src = &g_h2[((size_t)(bp * 256 + (cc + 1) * 16 + qci[j]) * 24 + 2 * oy + qr[j]) * 24 + qc16[j] * 2];
                unsigned dst = sb[nb] + (unsigned)((qci[j] * 192 + qr[j] * 24 + qc16[j] * 2) * 8);
                CPASYNC16(dst, src);
            }
            CPCOMMIT();
        }
        const ull* hsu = (const ull*)&hs[cc & 1][0];
        for (int cil = kh * 8; cil < kh * 8 + 8; cil++) {
            int g = cc * 16 + cil;
#pragma unroll
            for (int ky = 0; ky < 8; ky++) {
                ull in[24];
                const ulonglong2* ip = (const ulonglong2*)(hsu + cil * 192 + ky * 24);
#pragma unroll
                for (int j = 0; j < 12; j++) { ulonglong2 t = ip[j]; in[2*j] = t.x; in[2*j+1] = t.y; }
                const float* wp = &g_w2t[((g * 8 + ky) * 8) * 128 + co];
                ull w[8];
#pragma unroll
                for (int kx = 0; kx < 8; kx++) w[kx] = pack2(wp[kx * 128]);
#pragma unroll
                for (int kx = 0; kx < 8; kx++)
#pragma unroll
                    for (int ox = 0; ox < 9; ox++)
                        FMA2(acc[ox], in[2 * ox + kx], w[kx]);
            }
        }
        if (cc < 15) {
            CPWAIT0();
            __syncthreads();
        }
    }
    __syncthreads();
    ull* cm = (ull*)&hs[0][0];            // 128*9 ull = 9KB in buf 0
    if (kh == 1) {
#pragma unroll
        for (int ox = 0; ox < 9; ox++) cm[co * 9 + ox] = acc[ox];
    }
    __syncthreads();
    float* sq = (float*)&hs[1][0];        // 288 nodes * 8 comps = 2304 floats in buf 1
    if (kh == 0) {
        float bv = bias[co];
        int i = co >> 4, g2 = co & 15;
#pragma unroll
        for (int ox = 0; ox < 9; ox++) {
            ull o = cm[co * 9 + ox];
            sq[((0 * 144) + g2 * 9 + ox) * 8 + i] = f2lo(acc[ox]) + f2lo(o) + bv;
            sq[((1 * 144) + g2 * 9 + ox) * 8 + i] = f2hi(acc[ox]) + f2hi(o) + bv;
        }
    }
    __syncthreads();
    // fused primary-capsule squash: 288 nodes (2 batches x 144)
    for (int j = tid; j < 288; j += 256) {
        int bsel = j >= 144; int rem = j - bsel * 144;
        int g2 = rem / 9, ox = rem - g2 * 9;
        float v[8]; float sn = 0.f;
#pragma unroll
        for (int i = 0; i < 8; i++) { v[i] = sq[j * 8 + i]; sn = fmaf(v[i], v[i], sn); }
        float f = sqrtf(sn) / (1.f + sn);
        int b = bsel ? b1 : b0;
        int n = g2 * 81 + oy * 9 + ox;
        float4* up = (float4*)&g_u[(b * NNODES + n) * 8];
        up[0] = make_float4(v[0]*f, v[1]*f, v[2]*f, v[3]*f);
        up[1] = make_float4(v[4]*f, v[5]*f, v[6]*f, v[7]*f);
    }
}

// ---------------- priors[b,n,c,o] = sum_i u[b,n,i] * W[n,c,i,o]; store fp16x4 ----------------
__global__ __launch_bounds__(192) void k_priors(const float* __restrict__ route_w) {
    int n = blockIdx.x, by = blockIdx.y, tid = threadIdx.x;
    __shared__ float rw[NC * 8 * OD];   // 5504
    __shared__ float us[32 * 8];        // 256
    for (int idx = tid; idx < 5504; idx += 192) rw[idx] = route_w[n * 5504 + idx];
    for (int idx = tid; idx < 256; idx += 192) {
        int b = (idx >> 3) + by * 32, i = idx & 7;
        us[idx] = g_u[(b * NNODES + n) * 8 + i];
    }
    __syncthreads();
    if (tid < CO4) {
        int c = tid >> 2;
        int obase = (tid & 3) * 4;
        const float* rwc = &rw[c * 128 + obase];
        for (int bl = 0; bl < 32; bl++) {
            int b = by * 32 + bl;
            const float* ub = &us[bl * 8];
            float4 sum = make_float4(0.f, 0.f, 0.f, 0.f);
#pragma unroll
            for (int i = 0; i < 8; i++) {
                float u = ub[i];
                sum.x = fmaf(u, rwc[i * 16 + 0], sum.x);
                sum.y = fmaf(u, rwc[i * 16 + 1], sum.y);
                sum.z = fmaf(u, rwc[i * 16 + 2], sum.z);
                sum.w = fmaf(u, rwc[i * 16 + 3], sum.w);
            }
            __half2 p01 = __floats2half2_rn(sum.x, sum.y);
            __half2 p23 = __floats2half2_rn(sum.z, sum.w);
            ull v = (ull)h2u(p01) | ((ull)h2u(p23) << 32);
            g_pri[(size_t)(b * NNODES + n) * CO4 + tid] = v;
        }
    }
}

// ---------------- zero s (start of pipeline only) ----------------
__global__ void k_zero_s() {
    int i = blockIdx.x * 256 + threadIdx.x;
    if (i < NB * CO_TIMES_OD) g_s[i] = 0.f;
}

// ---------------- iter0: s = sum_n priors (27 nodes per block) ----------------
__global__ void k_reduce0() {
    int b = blockIdx.y, n0 = blockIdx.x * 27, tid = threadIdx.x;
    if (tid >= CO4) return;
    float4 acc = make_float4(0.f, 0.f, 0.f, 0.f);
    const ull* p = &g_pri[(size_t)(b * NNODES + n0) * CO4 + tid];
    for (int nn = 0; nn < 27; nn++) {
        float4 q = unpk(p[(size_t)nn * CO4]);
        acc.x += q.x; acc.y += q.y; acc.z += q.z; acc.w += q.w;
    }
    float* sp = &g_s[b * CO_TIMES_OD + tid * 4];
    atomicAdd(sp + 0, acc.x); atomicAdd(sp + 1, acc.y);
    atomicAdd(sp + 2, acc.z); atomicAdd(sp + 3, acc.w);
}

// ---------------- squash s -> caps0 (mode 0) or capsum = caps0 + squash(s) (mode 1); resets s ----------------
__global__ void k_squash_out(float scale, int mode) {
    int idx = blockIdx.x * 256 + threadIdx.x;
    if (idx >= NB * NC) return;
    float v[16]; float sn = 0.f;
#pragma unroll
    for (int o = 0; o < 16; o++) { v[o] = g_s[idx * 16 + o] * scale; sn = fmaf(v[o], v[o], sn); }
    float f = sqrtf(sn) / (1.f + sn);
#pragma unroll
    for (int o = 0; o < 16; o++) {
        float cap = v[o] * f;
        if (mode == 0) g_caps0[idx * 16 + o] = cap;
        else           g_capsum[idx * 16 + o] = g_caps0[idx * 16 + o] + cap;
        g_s[idx * 16 + o] = 0.f;
    }
}

// ---------------- routing iteration (no logits array, no max-sub in softmax) ----------------
__global__ __launch_bounds__(256) void k_iter(int sel) {
    int b = blockIdx.y;
    int wid = threadIdx.x >> 5;
    int lane = threadIdx.x & 31;
    int nbase = blockIdx.x * 81;          // grid.x = 16
    int c1 = lane;
    bool has2 = lane < (NC - 32);         // lanes 0..10 carry class 32+lane
    int c2 = lane + 32;

    __shared__ float s_acc[CO_TIMES_OD];
    for (int i = threadIdx.x; i < CO_TIMES_OD; i += 256) s_acc[i] = 0.f;

    const float* cb = sel ? &g_capsum[b * CO_TIMES_OD] : &g_caps0[b * CO_TIMES_OD];
    float cap1[16], cap2[16];
#pragma unroll
    for (int o = 0; o < 16; o++) cap1[o] = cb[c1 * OD + o];
#pragma unroll
    for (int o = 0; o < 16; o++) cap2[o] = has2 ? cb[c2 * OD + o] : 0.f;

    float acc1[16], acc2[16];
#pragma unroll
    for (int o = 0; o < 16; o++) { acc1[o] = 0.f; acc2[o] = 0.f; }
    __syncthreads();

    for (int nn = wid; nn < 81; nn += 8) {
        int n = nbase + nn;
        const ull* pp = &g_pri[((size_t)b * NNODES + n) * CO4];
        float pr1[16], pr2[16];
        {
            ulonglong2 q0 = *(const ulonglong2*)(pp + 4 * c1);
            ulonglong2 q1 = *(const ulonglong2*)(pp + 4 * c1 + 2);
            float4 a0 = unpk(q0.x), a1 = unpk(q0.y), a2 = unpk(q1.x), a3 = unpk(q1.y);
            pr1[0]=a0.x; pr1[1]=a0.y; pr1[2]=a0.z; pr1[3]=a0.w;
            pr1[4]=a1.x; pr1[5]=a1.y; pr1[6]=a1.z; pr1[7]=a1.w;
            pr1[8]=a2.x; pr1[9]=a2.y; pr1[10]=a2.z; pr1[11]=a2.w;
            pr1[12]=a3.x; pr1[13]=a3.y; pr1[14]=a3.z; pr1[15]=a3.w;
        }
        if (has2) {
            ulonglong2 q0 = *(const ulonglong2*)(pp + 4 * c2);
            ulonglong2 q1 = *(const ulonglong2*)(pp + 4 * c2 + 2);
            float4 a0 = unpk(q0.x), a1 = unpk(q0.y), a2 = unpk(q1.x), a3 = unpk(q1.y);
            pr2[0]=a0.x; pr2[1]=a0.y; pr2[2]=a0.z; pr2[3]=a0.w;
            pr2[4]=a1.x; pr2[5]=a1.y; pr2[6]=a1.z; pr2[7]=a1.w;
            pr2[8]=a2.x; pr2[9]=a2.y; pr2[10]=a2.z; pr2[11]=a2.w;
            pr2[12]=a3.x; pr2[13]=a3.y; pr2[14]=a3.z; pr2[15]=a3.w;
        } else {
#pragma unroll
            for (int o = 0; o < 16; o++) pr2[o] = 0.f;
        }
        float l1 = 0.f, l2 = 0.f;
#pragma unroll
        for (int o = 0; o < 16; o++) { l1 = fmaf(pr1[o], cap1[o], l1); l2 = fmaf(pr2[o], cap2[o], l2); }

        // softmax without max-subtraction: |l| is bounded (~<6), exp is safe
        float e1 = __expf(l1);
        float e2 = has2 ? __expf(l2) : 0.f;
        float ss = e1 + e2;
#pragma unroll
        for (int off = 16; off; off >>= 1) ss += __shfl_xor_sync(0xffffffffu, ss, off);
        float inv = 1.f / ss;
        float p1 = e1 * inv, p2 = e2 * inv;
#pragma unroll
        for (int o = 0; o < 16; o++) { acc1[o] = fmaf(p1, pr1[o], acc1[o]); acc2[o] = fmaf(p2, pr2[o], acc2[o]); }
    }
#pragma unroll
    for (int o = 0; o < 16; o++) atomicAdd(&s_acc[c1 * OD + o], acc1[o]);
    if (has2) {
#pragma unroll
        for (int o = 0; o < 16; o++) atomicAdd(&s_acc[c2 * OD + o], acc2[o]);
    }
    __syncthreads();
    if (threadIdx.x < CO4) {
        float4 a = *(const float4*)&s_acc[threadIdx.x * 4];
        float* sp = &g_s[b * CO_TIMES_OD + threadIdx.x * 4];
        atomicAdd(sp + 0, a.x); atomicAdd(sp + 1, a.y);
        atomicAdd(sp + 2, a.z); atomicAdd(sp + 3, a.w);
    }
}

// ---------------- final: scores = ||squash(s)|| = sn/(1+sn) ----------------
__global__ void k_final(float* __restrict__ out) {
    int idx = blockIdx.x * 256 + threadIdx.x;
    if (idx >= NB * NC) return;
    float sn = 0.f;
#pragma unroll
    for (int o = 0; o < 16; o++) { float v = g_s[idx * 16 + o]; sn = fmaf(v, v, sn); }
    out[idx] = sn / (1.f + sn);
}

// ---------------- launch ----------------
extern "C" void kernel_launch(void* const* d_in, const int* in_sizes, int n_in,
                              void* d_out, int out_size) {
    const float* x  = (const float*)d_in[0];
    const float* w1 = (const float*)d_in[1];
    const float* b1 = (const float*)d_in[2];
    const float* w2 = (const float*)d_in[3];
    const float* b2 = (const float*)d_in[4];
    const float* rw = (const float*)d_in[5];
    float* out = (float*)d_out;

    k_tr1<<<243, 256>>>(w1);
    k_tr2<<<dim3(512, 4), 256>>>(w2);
    k_conv1<<<dim3(24, 32), 256>>>(x, b1);
    k_prim<<<dim3(9, 32), 256>>>(b2);        // includes primary-capsule squash
    k_priors<<<dim3(NNODES, 2), 192>>>(rw);

    // iter 0: uniform probs (1/43 folded into squash scale) -> caps0
    k_zero_s<<<172, 256>>>();
    k_reduce0<<<dim3(48, NB), 192>>>();
    k_squash_out<<<11, 256>>>(1.f / 43.f, 0);    // writes caps0, zeroes s

    // iter 1: softmax(pr . caps0) -> s -> capsum = caps0 + squash(s)
    k_iter<<<dim3(16, NB), 256>>>(0);
    k_squash_out<<<11, 256>>>(1.f, 1);           // writes capsum, zeroes s

    // iter 2: softmax(pr . capsum) -> s -> scores
    k_iter<<<dim3(16, NB), 256>>>(1);
    k_final<<<11, 256>>>(out);
}

// round 10
// speedup vs baseline: 1.1671x; 1.1671x over previous
#include <cuda_runtime.h>
#include <cuda_fp16.h>
#include <cuda_bf16.h>
#include <math.h>

typedef unsigned long long ull;
typedef unsigned int u32;
typedef unsigned short u16;

// ---------------- problem constants ----------------
#define NB       64
#define NNODES   1296        // 16*81
#define NC       43
#define OD       16
#define CO_TIMES_OD 688      // 43*16
#define CO4      172         // 688/4

// packed f32x2 FMA (Blackwell sm_103a): two fp32 MACs per instruction, bit-exact fp32
#define FMA2(a,x,y) asm("fma.rn.f32x2 %0, %1, %2, %0;" : "+l"(a) : "l"(x), "l"(y))

#define CPASYNC16(dst_u32, src_ptr) \
    asm volatile("cp.async.cg.shared.global [%0], [%1], 16;" :: "r"(dst_u32), "l"(src_ptr))
#define CPCOMMIT()  asm volatile("cp.async.commit_group;" ::: "memory")
#define CPWAIT0()   asm volatile("cp.async.wait_group 0;" ::: "memory")

// bf16 mma: C[16x8] += A[16x16] * B[16x8], fp32 accum
#define MMA(d, A, b0, b1) \
    asm volatile("mma.sync.aligned.m16n8k16.row.col.f32.bf16.bf16.f32 " \
                 "{%0,%1,%2,%3},{%4,%5,%6,%7},{%8,%9},{%0,%1,%2,%3};" \
                 : "+f"(d[0]), "+f"(d[1]), "+f"(d[2]), "+f"(d[3]) \
                 : "r"(A[0]), "r"(A[1]), "r"(A[2]), "r"(A[3]), "r"(b0), "r"(b1))

static __device__ __forceinline__ float f2lo(ull v){ return __uint_as_float((unsigned)v); }
static __device__ __forceinline__ float f2hi(ull v){ return __uint_as_float((unsigned)(v>>32)); }
static __device__ __forceinline__ ull pack2(float w){ ull r; asm("mov.b64 %0, {%1, %1};" : "=l"(r) : "f"(w)); return r; }
static __device__ __forceinline__ u16 bfb(float v){ return __bfloat16_as_ushort(__float2bfloat16(v)); }

// ---------------- device scratch ----------------
__device__ float  g_w1t[62208];                    // conv1 weights scalar: [(ci*9+ky)*9+kx][co]
__device__ u32    g_wpk[2097152];                  // prim weights, mma-fragment packed [pl][cb8][ks1024][lane32][r4]
__device__ u16    g_hb[2][9437184];                // conv1 out bf16 hi/lo planes: [b][ci][y24][x24]
__device__ float  g_up[NB * NNODES * 8];           // pre-squash primary caps (atomic accum)
__device__ float  g_u[NB * NNODES * 8];            // squashed primary capsules
__device__ ull    g_pri[(size_t)NB * NNODES * CO4];// priors, fp16x4 packed (114MB)
__device__ float  g_s[NB * CO_TIMES_OD];
__device__ float  g_caps0[NB * CO_TIMES_OD];
__device__ float  g_capsum[NB * CO_TIMES_OD];

static __device__ __forceinline__ unsigned h2u(__half2 h){ return *reinterpret_cast<unsigned*>(&h); }
static __device__ __forceinline__ __half2 u2h(unsigned u){ return *reinterpret_cast<__half2*>(&u); }

static __device__ __forceinline__ float4 unpk(ull v) {
    float2 a = __half22float2(u2h((unsigned)v));
    float2 b = __half22float2(u2h((unsigned)(v >> 32)));
    return make_float4(a.x, a.y, b.x, b.y);
}

// ---------------- conv1 weight transpose ----------------
__global__ void k_tr1(const float* __restrict__ w) {
    int idx = blockIdx.x * 256 + threadIdx.x;
    if (idx >= 62208) return;
    int co = idx & 255; int r = idx >> 8;
    int kx = r % 9; int t = r / 9; int ky = t % 9; int ci = t / 9;
    g_w1t[idx] = w[co * 243 + ci * 81 + ky * 9 + kx];
}

// ---------------- prim weights -> bf16 hi/lo, mma A-fragment order ----------------
// entry idx = ((pl*8+cb)*1024 + ks)*128 + lane*4 + r
// row = cb*16 + lane/4 + (r&1)*8 ; k = ks*16 + (lane%3... (lane&3)*2 + (r>>1)*8
__global__ void k_wpk(const float* __restrict__ w) {
    int idx = blockIdx.x * 256 + threadIdx.x;      // 2,097,152 exact
    int r = idx & 3, lane = (idx >> 2) & 31, ks = (idx >> 7) & 1023;
    int cb = (idx >> 17) & 7, pl = idx >> 20;
    int row = cb * 16 + (lane >> 2) + (r & 1) * 8;
    int kk  = ks * 16 + (lane & 3) * 2 + (r >> 1) * 8;
    float v0 = w[row * 16384 + kk];
    float v1 = w[row * 16384 + kk + 1];
    if (pl) {
        v0 -= __bfloat162float(__float2bfloat16(v0));
        v1 -= __bfloat162float(__float2bfloat16(v1));
    }
    g_wpk[idx] = (u32)bfb(v0) | ((u32)bfb(v1) << 16);
}

// ---------------- conv1: batch-paired f32x2 -> bf16 hi/lo planes ----------------
__global__ __launch_bounds__(256, 2) void k_conv1(const float* __restrict__ x,
                                                  const float* __restrict__ bias) {
    int oy = blockIdx.x, bp = blockIdx.y;
    int b0 = bp, b1 = bp + 32;
    int co = threadIdx.x;
    __shared__ float2 xs[864];
    for (int idx = co; idx < 864; idx += 256) {
        int ci = idx / 288, rem = idx - ci * 288;
        int r = rem >> 5, col = rem & 31;
        int off = (ci * 32 + oy + r) * 32 + col;
        xs[idx] = make_float2(x[b0 * 3072 + off], x[b1 * 3072 + off]);
    }
    __syncthreads();
    const ull* xsu = (const ull*)xs;
    float bv = bias[co];
#pragma unroll 1
    for (int h = 0; h < 2; h++) {
        ull acc[12];
#pragma unroll
        for (int i = 0; i < 12; i++) acc[i] = 0ull;
        for (int ci = 0; ci < 3; ci++) {
#pragma unroll
            for (int ky = 0; ky < 9; ky++) {
                ull in[20];
                const ulonglong2* ip = (const ulonglong2*)(xsu + ci * 288 + ky * 32 + h * 12);
#pragma unroll
                for (int j = 0; j < 10; j++) { ulonglong2 t = ip[j]; in[2*j] = t.x; in[2*j+1] = t.y; }
                const float* wp = &g_w1t[((ci * 9 + ky) * 9) * 256 + co];
                ull w[9];
#pragma unroll
                for (int kx = 0; kx < 9; kx++) w[kx] = pack2(wp[kx * 256]);
#pragma unroll
                for (int kx = 0; kx < 9; kx++)
#pragma unroll
                    for (int ox = 0; ox < 12; ox++)
                        FMA2(acc[ox], in[ox + kx], w[kx]);
            }
        }
        // epilogue: relu, bf16 hi/lo split, packed stores for both batches
#pragma unroll
        for (int bs = 0; bs < 2; bs++) {
            int b = bs ? b1 : b0;
            float v[12];
#pragma unroll
            for (int ox = 0; ox < 12; ox++)
                v[ox] = fmaxf((bs ? f2hi(acc[ox]) : f2lo(acc[ox])) + bv, 0.f);
            u32 ph[6], plo[6];
#pragma unroll
            for (int j = 0; j < 6; j++) {
                float a = v[2*j], c = v[2*j+1];
                __nv_bfloat16 ah = __float2bfloat16(a), ch = __float2bfloat16(c);
                float al = a - __bfloat162float(ah), cl = c - __bfloat162float(ch);
                ph[j]  = (u32)__bfloat16_as_ushort(ah) | ((u32)__bfloat16_as_ushort(ch) << 16);
                plo[j] = (u32)bfb(al) | ((u32)bfb(cl) << 16);
            }
            int halfidx = (b * 256 + co) * 576 + oy * 24 + h * 12;
#pragma unroll
            for (int pl = 0; pl < 2; pl++) {
                u32* p = (u32*)&g_hb[pl][halfidx];
                const u32* s = pl ? plo : ph;
                if (h == 0) {
                    *(uint4*)p = make_uint4(s[0], s[1], s[2], s[3]);
                    *(uint2*)(p + 4) = make_uint2(s[4], s[5]);
                } else {
                    *(uint2*)p = make_uint2(s[0], s[1]);
                    *(uint4*)(p + 2) = make_uint4(s[2], s[3], s[4], s[5]);
                }
            }
        }
    }
}

// ---------------- zero pre-squash buffer ----------------
__global__ void k_zero_up() {
    int i = blockIdx.x * 256 + threadIdx.x;
    if (i < NB * NNODES * 8) g_up[i] = 0.f;
}

// ---------------- prim conv via mma.sync bf16 3-term split ----------------
// GEMM: C[co 128][n 72(+8 pad)] += W[co][k] * X[k][n], k=(ci,ky,kx), n=(b,ox)
// grid (9 oy, 8 bgroup, 2 ci-half), 256 threads = 8 warps (4 m x 2 n)
__global__ __launch_bounds__(256) void k_prim() {
    int oy = blockIdx.x, bg = blockIdx.y, z = blockIdx.z;
    int tid = threadIdx.x, lane = tid & 31, warp = tid >> 5;
    int warp_m = warp & 3, warp_n = warp >> 2;
    __shared__ u16 sbm[2][4096];       // [buf][pl 2][j 8][ky 8][32 cols]
    u32 sb0 = (u32)__cvta_generic_to_shared(&sbm[0][0]);

    // zero pad cols 24..31 (one row per thread; 256 rows total over 2 buffers)
    { int buf = tid >> 7, rowi = tid & 127;
      *(uint4*)&sbm[buf][rowi * 32 + 24] = make_uint4(0, 0, 0, 0); }

    // B n-decomposition per n-fragment (lane-constant)
    int cB[5];
#pragma unroll
    for (int nf = 0; nf < 5; nf++) {
        int n = warp_n * 40 + nf * 8 + (lane >> 2);
        int j = n / 10, ox = n - j * 10;
        cB[nf] = j * 256 + 2 * ox + (lane & 3) * 2;
    }

    float acc[2][5][4];
#pragma unroll
    for (int a = 0; a < 2; a++)
#pragma unroll
        for (int b = 0; b < 5; b++)
#pragma unroll
            for (int c = 0; c < 4; c++) acc[a][b][c] = 0.f;

    // cp.async stage: 384 x 16B per chunk (chunk = 1 ci, 2 planes, 8 b, 8 ky, 3 segs)
    int ci0 = z * 128;
#pragma unroll
    for (int rep = 0; rep < 2; rep++) {
        int q = tid + rep * 256;
        if (q < 384) {
            int seg = q % 3, t = q / 3;
            int ky = t & 7, j = (t >> 3) & 7, pl = t >> 6;
            const u16* src = &g_hb[pl][((size_t)((bg * 8 + j) * 256 + ci0)) * 576 + (2 * oy + ky) * 24 + seg * 8];
            u32 dst = sb0 + (u32)((((pl * 8 + j) * 8 + ky) * 32 + seg * 8) * 2);
            CPASYNC16(dst, src);
        }
    }
    CPCOMMIT(); CPWAIT0();
    __syncthreads();

#pragma unroll 1
    for (int cc = 0; cc < 128; cc++) {
        if (cc < 127) {
            int nb = (cc + 1) & 1;
            int ci = ci0 + cc + 1;
#pragma unroll
            for (int rep = 0; rep < 2; rep++) {
                int q = tid + rep * 256;
                if (q < 384) {
                    int seg = q % 3, t = q / 3;
                    int ky = t & 7, j = (t >> 3) & 7, pl = t >> 6;
                    const u16* src = &g_hb[pl][((size_t)((bg * 8 + j) * 256 + ci)) * 576 + (2 * oy + ky) * 24 + seg * 8];
                    u32 dst = sb0 + (u32)(nb * 8192 + (((pl * 8 + j) * 8 + ky) * 32 + seg * 8) * 2);
                    CPASYNC16(dst, src);
                }
            }
            CPCOMMIT();
        }
        const u16* sbuf = &sbm[cc & 1][0];
#pragma unroll
        for (int ks = 0; ks < 4; ks++) {
            int ksg = (ci0 + cc) * 4 + ks;
            u32 A[2][2][4];   // [pl][mf][4 regs]
#pragma unroll
            for (int pl = 0; pl < 2; pl++)
#pragma unroll
                for (int mf = 0; mf < 2; mf++) {
                    const uint4* ap = (const uint4*)(g_wpk + (size_t)((pl * 8 + warp_m * 2 + mf) * 1024 + ksg) * 128);
                    uint4 q = ap[lane];
                    A[pl][mf][0] = q.x; A[pl][mf][1] = q.y; A[pl][mf][2] = q.z; A[pl][mf][3] = q.w;
                }
#pragma unroll
            for (int nf = 0; nf < 5; nf++) {
                u32 bh0 = *(const u32*)&sbuf[cB[nf] + (2 * ks) * 32];
                u32 bh1 = *(const u32*)&sbuf[cB[nf] + (2 * ks + 1) * 32];
                u32 bl0 = *(const u32*)&sbuf[2048 + cB[nf] + (2 * ks) * 32];
                u32 bl1 = *(const u32*)&sbuf[2048 + cB[nf] + (2 * ks + 1) * 32];
#pragma unroll
                for (int mf = 0; mf < 2; mf++) {
                    MMA(acc[mf][nf], A[0][mf], bh0, bh1);   // hi*hi
                    MMA(acc[mf][nf], A[0][mf], bl0, bl1);   // hi*lo
                    MMA(acc[mf][nf], A[1][mf], bh0, bh1);   // lo*hi
                }
            }
        }
        if (cc < 127) {
            CPWAIT0();
            __syncthreads();
        }
    }

    // epilogue: scatter partial sums
#pragma unroll
    for (int mf = 0; mf < 2; mf++)
#pragma unroll
        for (int nf = 0; nf < 5; nf++)
#pragma unroll
            for (int e = 0; e < 4; e++) {
                int co = warp_m * 32 + mf * 16 + (lane >> 2) + (e >> 1) * 8;
                int n = warp_n * 40 + nf * 8 + (lane & 3) * 2 + (e & 1);
                int j = n / 10, ox = n - j * 10;
                if (ox < 9) {
                    int b = bg * 8 + j;
                    int node = (co & 15) * 81 + oy * 9 + ox;
                    atomicAdd(&g_up[((size_t)b * NNODES + node) * 8 + (co >> 4)], acc[mf][nf][e]);
                }
            }
}

// ---------------- squash primary capsules (adds bias) ----------------
__global__ void k_squash_u(const float* __restrict__ bias) {
    int idx = blockIdx.x * 256 + threadIdx.x;
    if (idx >= NB * NNODES) return;
    int n = idx % NNODES;
    int g2 = n / 81;
    float v[8]; float sn = 0.f;
#pragma unroll
    for (int i = 0; i < 8; i++) {
        v[i] = g_up[idx * 8 + i] + bias[i * 16 + g2];
        sn = fmaf(v[i], v[i], sn);
    }
    float f = sqrtf(sn) / (1.f + sn);
#pragma unroll
    for (int i = 0; i < 8; i++) g_u[idx * 8 + i] = v[i] * f;
}

// ---------------- priors[b,n,c,o] = sum_i u[b,n,i] * W[n,c,i,o]; store fp16x4 ----------------
__global__ __launch_bounds__(192) void k_priors(const float* __restrict__ route_w) {
    int n = blockIdx.x, by = blockIdx.y, tid = threadIdx.x;
    __shared__ float rw[NC * 8 * OD];
    __shared__ float us[32 * 8];
    for (int idx = tid; idx < 5504; idx += 192) rw[idx] = route_w[n * 5504 + idx];
    for (int idx = tid; idx < 256; idx += 192) {
        int b = (idx >> 3) + by * 32, i = idx & 7;
        us[idx] = g_u[(b * NNODES + n) * 8 + i];
    }
    __syncthreads();
    if (tid < CO4) {
        int c = tid >> 2;
        int obase = (tid & 3) * 4;
        const float* rwc = &rw[c * 128 + obase];
        for (int bl = 0; bl < 32; bl++) {
            int b = by * 32 + bl;
            const float* ub = &us[bl * 8];
            float4 sum = make_float4(0.f, 0.f, 0.f, 0.f);
#pragma unroll
            for (int i = 0; i < 8; i++) {
                float u = ub[i];
                sum.x = fmaf(u, rwc[i * 16 + 0], sum.x);
                sum.y = fmaf(u, rwc[i * 16 + 1], sum.y);
                sum.z = fmaf(u, rwc[i * 16 + 2], sum.z);
                sum.w = fmaf(u, rwc[i * 16 + 3], sum.w);
            }
            __half2 p01 = __floats2half2_rn(sum.x, sum.y);
            __half2 p23 = __floats2half2_rn(sum.z, sum.w);
            ull v = (ull)h2u(p01) | ((ull)h2u(p23) << 32);
            g_pri[(size_t)(b * NNODES + n) * CO4 + tid] = v;
        }
    }
}

// ---------------- zero s ----------------
__global__ void k_zero_s() {
    int i = blockIdx.x * 256 + threadIdx.x;
    if (i < NB * CO_TIMES_OD) g_s[i] = 0.f;
}

// ---------------- iter0: s = sum_n priors ----------------
__global__ void k_reduce0() {
    int b = blockIdx.y, n0 = blockIdx.x * 27, tid = threadIdx.x;
    if (tid >= CO4) return;
    float4 acc = make_float4(0.f, 0.f, 0.f, 0.f);
    const ull* p = &g_pri[(size_t)(b * NNODES + n0) * CO4 + tid];
    for (int nn = 0; nn < 27; nn++) {
        float4 q = unpk(p[(size_t)nn * CO4]);
        acc.x += q.x; acc.y += q.y; acc.z += q.z; acc.w += q.w;
    }
    float* sp = &g_s[b * CO_TIMES_OD + tid * 4];
    atomicAdd(sp + 0, acc.x); atomicAdd(sp + 1, acc.y);
    atomicAdd(sp + 2, acc.z); atomicAdd(sp + 3, acc.w);
}

// ---------------- squash s -> caps0 / capsum; resets s ----------------
__global__ void k_squash_out(float scale, int mode) {
    int idx = blockIdx.x * 256 + threadIdx.x;
    if (idx >= NB * NC) return;
    float v[16]; float sn = 0.f;
#pragma unroll
    for (int o = 0; o < 16; o++) { v[o] = g_s[idx * 16 + o] * scale; sn = fmaf(v[o], v[o], sn); }
    float f = sqrtf(sn) / (1.f + sn);
#pragma unroll
    for (int o = 0; o < 16; o++) {
        float cap = v[o] * f;
        if (mode == 0) g_caps0[idx * 16 + o] = cap;
        else           g_capsum[idx * 16 + o] = g_caps0[idx * 16 + o] + cap;
        g_s[idx * 16 + o] = 0.f;
    }
}

// ---------------- routing iteration ----------------
__global__ __launch_bounds__(256) void k_iter(int sel) {
    int b = blockIdx.y;
    int wid = threadIdx.x >> 5;
    int lane = threadIdx.x & 31;
    int nbase = blockIdx.x * 81;
    int c1 = lane;
    bool has2 = lane < (NC - 32);
    int c2 = lane + 32;

    __shared__ float s_acc[CO_TIMES_OD];
    for (int i = threadIdx.x; i < CO_TIMES_OD; i += 256) s_acc[i] = 0.f;

    const float* cb = sel ? &g_capsum[b * CO_TIMES_OD] : &g_caps0[b * CO_TIMES_OD];
    float cap1[16], cap2[16];
#pragma unroll
    for (int o = 0; o < 16; o++) cap1[o] = cb[c1 * OD + o];
#pragma unroll
    for (int o = 0; o < 16; o++) cap2[o] = has2 ? cb[c2 * OD + o] : 0.f;

    float acc1[16], acc2[16];
#pragma unroll
    for (int o = 0; o < 16; o++) { acc1[o] = 0.f; acc2[o] = 0.f; }
    __syncthreads();

    for (int nn = wid; nn < 81; nn += 8) {
        int n = nbase + nn;
        const ull* pp = &g_pri[((size_t)b * NNODES + n) * CO4];
        float pr1[16], pr2[16];
        {
            ulonglong2 q0 = *(const ulonglong2*)(pp + 4 * c1);
            ulonglong2 q1 = *(const ulonglong2*)(pp + 4 * c1 + 2);
            float4 a0 = unpk(q0.x), a1 = unpk(q0.y), a2 = unpk(q1.x), a3 = unpk(q1.y);
            pr1[0]=a0.x; pr1[1]=a0.y; pr1[2]=a0.z; pr1[3]=a0.w;
            pr1[4]=a1.x; pr1[5]=a1.y; pr1[6]=a1.z; pr1[7]=a1.w;
            pr1[8]=a2.x; pr1[9]=a2.y; pr1[10]=a2.z; pr1[11]=a2.w;
            pr1[12]=a3.x; pr1[13]=a3.y; pr1[14]=a3.z; pr1[15]=a3.w;
        }
        if (has2) {
            ulonglong2 q0 = *(const ulonglong2*)(pp + 4 * c2);
            ulonglong2 q1 = *(const ulonglong2*)(pp + 4 * c2 + 2);
            float4 a0 = unpk(q0.x), a1 = unpk(q0.y), a2 = unpk(q1.x), a3 = unpk(q1.y);
            pr2[0]=a0.x; pr2[1]=a0.y; pr2[2]=a0.z; pr2[3]=a0.w;
            pr2[4]=a1.x; pr2[5]=a1.y; pr2[6]=a1.z; pr2[7]=a1.w;
            pr2[8]=a2.x; pr2[9]=a2.y; pr2[10]=a2.z; pr2[11]=a2.w;
            pr2[12]=a3.x; pr2[13]=a3.y; pr2[14]=a3.z; pr2[15]=a3.w;
        } else {
#pragma unroll
            for (int o = 0; o < 16; o++) pr2[o] = 0.f;
        }
        float l1 = 0.f, l2 = 0.f;
#pragma unroll
        for (int o = 0; o < 16; o++) { l1 = fmaf(pr1[o], cap1[o], l1); l2 = fmaf(pr2[o], cap2[o], l2); }

        float e1 = __expf(l1);
        float e2 = has2 ? __expf(l2) : 0.f;
        float ss = e1 + e2;
#pragma unroll
        for (int off = 16; off; off >>= 1) ss += __shfl_xor_sync(0xffffffffu, ss, off);
        float inv = 1.f / ss;
        float p1 = e1 * inv, p2 = e2 * inv;
#pragma unroll
        for (int o = 0; o < 16; o++) { acc1[o] = fmaf(p1, pr1[o], acc1[o]); acc2[o] = fmaf(p2, pr2[o], acc2[o]); }
    }
#pragma unroll
    for (int o = 0; o < 16; o++) atomicAdd(&s_acc[c1 * OD + o], acc1[o]);
    if (has2) {
#pragma unroll
        for (int o = 0; o < 16; o++) atomicAdd(&s_acc[c2 * OD + o], acc2[o]);
    }
    __syncthreads();
    if (threadIdx.x < CO4) {
        float4 a = *(const float4*)&s_acc[threadIdx.x * 4];
        float* sp = &g_s[b * CO_TIMES_OD + threadIdx.x * 4];
        atomicAdd(sp + 0, a.x); atomicAdd(sp + 1, a.y);
        atomicAdd(sp + 2, a.z); atomicAdd(sp + 3, a.w);
    }
}

// ---------------- final ----------------
__global__ void k_final(float* __restrict__ out) {
    int idx = blockIdx.x * 256 + threadIdx.x;
    if (idx >= NB * NC) return;
    float sn = 0.f;
#pragma unroll
    for (int o = 0; o < 16; o++) { float v = g_s[idx * 16 + o]; sn = fmaf(v, v, sn); }
    out[idx] = sn / (1.f + sn);
}

// ---------------- launch ----------------
extern "C" void kernel_launch(void* const* d_in, const int* in_sizes, int n_in,
                              void* d_out, int out_size) {
    const float* x  = (const float*)d_in[0];
    const float* w1 = (const float*)d_in[1];
    const float* b1 = (const float*)d_in[2];
    const float* w2 = (const float*)d_in[3];
    const float* b2 = (const float*)d_in[4];
    const float* rw = (const float*)d_in[5];
    float* out = (float*)d_out;

    k_tr1<<<243, 256>>>(w1);
    k_wpk<<<8192, 256>>>(w2);
    k_conv1<<<dim3(24, 32), 256>>>(x, b1);
    k_zero_up<<<(NB * NNODES * 8 + 255) / 256, 256>>>();
    k_prim<<<dim3(9, 8, 2), 256>>>();
    k_squash_u<<<(NB * NNODES + 255) / 256, 256>>>(b2);
    k_priors<<<dim3(NNODES, 2), 192>>>(rw);

    // iter 0: uniform probs (1/43 folded into squash scale) -> caps0
    k_zero_s<<<172, 256>>>();
    k_reduce0<<<dim3(48, NB), 192>>>();
    k_squash_out<<<11, 256>>>(1.f / 43.f, 0);

    // iter 1: softmax(pr . caps0) -> s -> capsum = caps0 + squash(s)
    k_iter<<<dim3(16, NB), 256>>>(0);
    k_squash_out<<<11, 256>>>(1.f, 1);

    // iter 2: softmax(pr . capsum) -> s -> scores
    k_iter<<<dim3(16, NB), 256>>>(1);
    k_final<<<11, 256>>>(out);
}

// round 12
// speedup vs baseline: 1.5623x; 1.3386x over previous
#include <cuda_runtime.h>
#include <cuda_fp16.h>
#include <cuda_bf16.h>
#include <math.h>

typedef unsigned long long ull;
typedef unsigned int u32;
typedef unsigned short u16;

// ---------------- problem constants ----------------
#define NB       64
#define NNODES   1296        // 16*81
#define NC       43
#define OD       16
#define CO_TIMES_OD 688      // 43*16
#define CO4      172         // 688/4

// packed f32x2 FMA (Blackwell sm_103a): two fp32 MACs per instruction, bit-exact fp32
#define FMA2(a,x,y) asm("fma.rn.f32x2 %0, %1, %2, %0;" : "+l"(a) : "l"(x), "l"(y))

#define CPASYNC16(dst_u32, src_ptr) \
    asm volatile("cp.async.cg.shared.global [%0], [%1], 16;" :: "r"(dst_u32), "l"(src_ptr))
#define CPCOMMIT()  asm volatile("cp.async.commit_group;" ::: "memory")
#define CPWAIT0()   asm volatile("cp.async.wait_group 0;" ::: "memory")

// fp16 mma: C[16x8] += A[16x16] * B[16x8], fp32 accum
#define MMA(d, A, b0, b1) \
    asm volatile("mma.sync.aligned.m16n8k16.row.col.f32.f16.f16.f32 " \
                 "{%0,%1,%2,%3},{%4,%5,%6,%7},{%8,%9},{%0,%1,%2,%3};" \
                 : "+f"(d[0]), "+f"(d[1]), "+f"(d[2]), "+f"(d[3]) \
                 : "r"(A[0]), "r"(A[1]), "r"(A[2]), "r"(A[3]), "r"(b0), "r"(b1))

static __device__ __forceinline__ float f2lo(ull v){ return __uint_as_float((unsigned)v); }
static __device__ __forceinline__ float f2hi(ull v){ return __uint_as_float((unsigned)(v>>32)); }
static __device__ __forceinline__ ull pack2(float w){ ull r; asm("mov.b64 %0, {%1, %1};" : "=l"(r) : "f"(w)); return r; }
static __device__ __forceinline__ u16 h16(float v){ return __half_as_ushort(__float2half_rn(v)); }

// ---------------- device scratch ----------------
__device__ float  g_w1t[62208];                    // conv1 weights scalar: [(ci*9+ky)*9+kx][co]
__device__ u32    g_wpk[2097152];                  // prim weights fp16 hi/lo, mma A-fragment packed
__device__ u16    g_hb[9437184];                   // conv1 out fp16: [b][ci][y24][x24]
__device__ float  g_up[NB * NNODES * 8];           // pre-squash primary caps (atomic accum)
__device__ float  g_u[NB * NNODES * 8];            // squashed primary capsules
__device__ ull    g_pri[(size_t)NB * NNODES * CO4];// priors, fp16x4 packed (114MB)
__device__ float  g_s[NB * CO_TIMES_OD];
__device__ float  g_caps0[NB * CO_TIMES_OD];
__device__ float  g_capsum[NB * CO_TIMES_OD];

static __device__ __forceinline__ unsigned h2u(__half2 h){ return *reinterpret_cast<unsigned*>(&h); }
static __device__ __forceinline__ __half2 u2h(unsigned u){ return *reinterpret_cast<__half2*>(&u); }

static __device__ __forceinline__ float4 unpk(ull v) {
    float2 a = __half22float2(u2h((unsigned)v));
    float2 b = __half22float2(u2h((unsigned)(v >> 32)));
    return make_float4(a.x, a.y, b.x, b.y);
}

// ---------------- conv1 weight transpose ----------------
__global__ void k_tr1(const float* __restrict__ w) {
    int idx = blockIdx.x * 256 + threadIdx.x;
    if (idx >= 62208) return;
    int co = idx & 255; int r = idx >> 8;
    int kx = r % 9; int t = r / 9; int ky = t % 9; int ci = t / 9;
    g_w1t[idx] = w[co * 243 + ci * 81 + ky * 9 + kx];
}

// ---------------- prim weights -> fp16 hi/lo, mma A-fragment order ----------------
// entry idx = ((pl*8+cb)*1024 + ks)*128 + lane*4 + r
// row = cb*16 + lane/4 + (r&1)*8 ; k = ks*16 + (lane&3)*2 + (r>>1)*8
__global__ void k_wpk(const float* __restrict__ w) {
    int idx = blockIdx.x * 256 + threadIdx.x;      // 2,097,152 exact
    int r = idx & 3, lane = (idx >> 2) & 31, ks = (idx >> 7) & 1023;
    int cb = (idx >> 17) & 7, pl = idx >> 20;
    int row = cb * 16 + (lane >> 2) + (r & 1) * 8;
    int kk  = ks * 16 + (lane & 3) * 2 + (r >> 1) * 8;
    float v0 = w[row * 16384 + kk];
    float v1 = w[row * 16384 + kk + 1];
    if (pl) {
        v0 -= __half2float(__float2half_rn(v0));
        v1 -= __half2float(__float2half_rn(v1));
    }
    g_wpk[idx] = (u32)h16(v0) | ((u32)h16(v1) << 16);
}

// ---------------- conv1: batch-paired f32x2 -> fp16 plane ----------------
__global__ __launch_bounds__(256, 2) void k_conv1(const float* __restrict__ x,
                                                  const float* __restrict__ bias) {
    int oy = blockIdx.x, bp = blockIdx.y;
    int b0 = bp, b1 = bp + 32;
    int co = threadIdx.x;
    __shared__ float2 xs[864];
    for (int idx = co; idx < 864; idx += 256) {
        int ci = idx / 288, rem = idx - ci * 288;
        int r = rem >> 5, col = rem & 31;
        int off = (ci * 32 + oy + r) * 32 + col;
        xs[idx] = make_float2(x[b0 * 3072 + off], x[b1 * 3072 + off]);
    }
    __syncthreads();
    const ull* xsu = (const ull*)xs;
    float bv = bias[co];
#pragma unroll 1
    for (int h = 0; h < 2; h++) {
        ull acc[12];
#pragma unroll
        for (int i = 0; i < 12; i++) acc[i] = 0ull;
        for (int ci = 0; ci < 3; ci++) {
#pragma unroll
            for (int ky = 0; ky < 9; ky++) {
                ull in[20];
                const ulonglong2* ip = (const ulonglong2*)(xsu + ci * 288 + ky * 32 + h * 12);
#pragma unroll
                for (int j = 0; j < 10; j++) { ulonglong2 t = ip[j]; in[2*j] = t.x; in[2*j+1] = t.y; }
                const float* wp = &g_w1t[((ci * 9 + ky) * 9) * 256 + co];
                ull w[9];
#pragma unroll
                for (int kx = 0; kx < 9; kx++) w[kx] = pack2(wp[kx * 256]);
#pragma unroll
                for (int kx = 0; kx < 9; kx++)
#pragma unroll
                    for (int ox = 0; ox < 12; ox++)
                        FMA2(acc[ox], in[ox + kx], w[kx]);
            }
        }
#pragma unroll
        for (int bs = 0; bs < 2; bs++) {
            int b = bs ? b1 : b0;
            u32 p6[6];
#pragma unroll
            for (int j = 0; j < 6; j++) {
                float a = fmaxf((bs ? f2hi(acc[2*j])   : f2lo(acc[2*j]))   + bv, 0.f);
                float c = fmaxf((bs ? f2hi(acc[2*j+1]) : f2lo(acc[2*j+1])) + bv, 0.f);
                p6[j] = (u32)h16(a) | ((u32)h16(c) << 16);
            }
            u32* p = (u32*)&g_hb[(b * 256 + co) * 576 + oy * 24 + h * 12];
            if (h == 0) {
                *(uint4*)p = make_uint4(p6[0], p6[1], p6[2], p6[3]);
                *(uint2*)(p + 4) = make_uint2(p6[4], p6[5]);
            } else {
                *(uint2*)p = make_uint2(p6[0], p6[1]);
                *(uint4*)(p + 2) = make_uint4(p6[2], p6[3], p6[4], p6[5]);
            }
        }
    }
}

// ---------------- zero pre-squash buffer ----------------
__global__ void k_zero_up() {
    int i = blockIdx.x * 256 + threadIdx.x;
    if (i < NB * NNODES * 8) g_up[i] = 0.f;
}

// ---------------- prim conv via mma.sync fp16 weight-split (2 terms) ----------------
// GEMM: C[co 128][n 72(+8 pad)] += W[co][k] * X[k][n], k=(ci,ky,kx), n=(b,ox)
// grid (9 oy, 8 bgroup, 4 ci-quarter), 256 threads = 8 warps (4 m x 2 n)
__global__ __launch_bounds__(256) void k_prim() {
    int oy = blockIdx.x, bg = blockIdx.y, z = blockIdx.z;
    int tid = threadIdx.x, lane = tid & 31, warp = tid >> 5;
    int warp_m = warp & 3, warp_n = warp >> 2;
    __shared__ u16 sbm[2][2048];       // [buf][j 8][ky 8][32 cols]
    u32 sb0 = (u32)__cvta_generic_to_shared(&sbm[0][0]);

    // zero pad cols 24..31 (128 rows over 2 buffers)
    if (tid < 128) {
        int buf = tid >> 6, rowi = tid & 63;
        *(uint4*)&sbm[buf][rowi * 32 + 24] = make_uint4(0, 0, 0, 0);
    }

    // B n-decomposition per n-fragment (lane-constant)
    int cB[5];
#pragma unroll
    for (int nf = 0; nf < 5; nf++) {
        int n = warp_n * 40 + nf * 8 + (lane >> 2);
        int j = n / 10, ox = n - j * 10;
        cB[nf] = j * 256 + 2 * ox + (lane & 3) * 2;
    }

    float acc[2][5][4];
#pragma unroll
    for (int a = 0; a < 2; a++)
#pragma unroll
        for (int b = 0; b < 5; b++)
#pragma unroll
            for (int c = 0; c < 4; c++) acc[a][b][c] = 0.f;

    // cp.async stage: 192 x 16B per chunk (chunk = 1 ci, 8 b, 8 ky, 3 segs)
    int ci0 = z * 64;
    if (tid < 192) {
        int seg = tid % 3, t = tid / 3;
        int ky = t & 7, j = t >> 3;
        const u16* src = &g_hb[((size_t)((bg * 8 + j) * 256 + ci0)) * 576 + (2 * oy + ky) * 24 + seg * 8];
        u32 dst = sb0 + (u32)(((j * 8 + ky) * 32 + seg * 8) * 2);
        CPASYNC16(dst, src);
    }
    CPCOMMIT(); CPWAIT0();
    __syncthreads();

#pragma unroll 1
    for (int cc = 0; cc < 64; cc++) {
        if (cc < 63) {
            int nb = (cc + 1) & 1;
            int ci = ci0 + cc + 1;
            if (tid < 192) {
                int seg = tid % 3, t = tid / 3;
                int ky = t & 7, j = t >> 3;
                const u16* src = &g_hb[((size_t)((bg * 8 + j) * 256 + ci)) * 576 + (2 * oy + ky) * 24 + seg * 8];
                u32 dst = sb0 + (u32)(nb * 4096 + ((j * 8 + ky) * 32 + seg * 8) * 2);
                CPASYNC16(dst, src);
            }
            CPCOMMIT();
        }
        const u16* sbuf = &sbm[cc & 1][0];
#pragma unroll
        for (int ks = 0; ks < 4; ks++) {
            int ksg = (ci0 + cc) * 4 + ks;
            u32 A[2][2][4];   // [pl][mf][4 regs]
#pragma unroll
            for (int pl = 0; pl < 2; pl++)
#pragma unroll
                for (int mf = 0; mf < 2; mf++) {
                    const uint4* ap = (const uint4*)(g_wpk + (size_t)((pl * 8 + warp_m * 2 + mf) * 1024 + ksg) * 128);
                    uint4 q = ap[lane];
                    A[pl][mf][0] = q.x; A[pl][mf][1] = q.y; A[pl][mf][2] = q.z; A[pl][mf][3] = q.w;
                }
#pragma unroll
            for (int nf = 0; nf < 5; nf++) {
                u32 b0 = *(const u32*)&sbuf[cB[nf] + (2 * ks) * 32];
                u32 b1 = *(const u32*)&sbuf[cB[nf] + (2 * ks + 1) * 32];
#pragma unroll
                for (int mf = 0; mf < 2; mf++) {
                    MMA(acc[mf][nf], A[0][mf], b0, b1);   // W_hi * X
                    MMA(acc[mf][nf], A[1][mf], b0, b1);   // W_lo * X
                }
            }
        }
        if (cc < 63) {
            CPWAIT0();
            __syncthreads();
        }
    }

    // epilogue: scatter partial sums
#pragma unroll
    for (int mf = 0; mf < 2; mf++)
#pragma unroll
        for (int nf = 0; nf < 5; nf++)
#pragma unroll
            for (int e = 0; e < 4; e++) {
                int co = warp_m * 32 + mf * 16 + (lane >> 2) + (e >> 1) * 8;
                int n = warp_n * 40 + nf * 8 + (lane & 3) * 2 + (e & 1);
                int j = n / 10, ox = n - j * 10;
                if (ox < 9) {
                    int b = bg * 8 + j;
                    int node = (co & 15) * 81 + oy * 9 + ox;
                    atomicAdd(&g_up[((size_t)b * NNODES + node) * 8 + (co >> 4)], acc[mf][nf][e]);
                }
            }
}

// ---------------- squash primary capsules (adds bias) ----------------
__global__ void k_squash_u(const float* __restrict__ bias) {
    int idx = blockIdx.x * 256 + threadIdx.x;
    if (idx >= NB * NNODES) return;
    int n = idx % NNODES;
    int g2 = n / 81;
    float v[8]; float sn = 0.f;
#pragma unroll
    for (int i = 0; i < 8; i++) {
        v[i] = g_up[idx * 8 + i] + bias[i * 16 + g2];
        sn = fmaf(v[i], v[i], sn);
    }
    float f = sqrtf(sn) / (1.f + sn);
#pragma unroll
    for (int i = 0; i < 8; i++) g_u[idx * 8 + i] = v[i] * f;
}

// ---------------- priors[b,n,c,o] = sum_i u[b,n,i] * W[n,c,i,o]; store fp16x4 ----------------
__global__ __launch_bounds__(192) void k_priors(const float* __restrict__ route_w) {
    int n = blockIdx.x, by = blockIdx.y, tid = threadIdx.x;
    __shared__ float rw[NC * 8 * OD];
    __shared__ float us[32 * 8];
    for (int idx = tid; idx < 5504; idx += 192) rw[idx] = route_w[n * 5504 + idx];
    for (int idx = tid; idx < 256; idx += 192) {
        int b = (idx >> 3) + by * 32, i = idx & 7;
        us[idx] = g_u[(b * NNODES + n) * 8 + i];
    }
    __syncthreads();
    if (tid < CO4) {
        int c = tid >> 2;
        int obase = (tid & 3) * 4;
        const float* rwc = &rw[c * 128 + obase];
        for (int bl = 0; bl < 32; bl++) {
            int b = by * 32 + bl;
            const float* ub = &us[bl * 8];
            float4 sum = make_float4(0.f, 0.f, 0.f, 0.f);
#pragma unroll
            for (int i = 0; i < 8; i++) {
                float u = ub[i];
                sum.x = fmaf(u, rwc[i * 16 + 0], sum.x);
                sum.y = fmaf(u, rwc[i * 16 + 1], sum.y);
                sum.z = fmaf(u, rwc[i * 16 + 2], sum.z);
                sum.w = fmaf(u, rwc[i * 16 + 3], sum.w);
            }
            __half2 p01 = __floats2half2_rn(sum.x, sum.y);
            __half2 p23 = __floats2half2_rn(sum.z, sum.w);
            ull v = (ull)h2u(p01) | ((ull)h2u(p23) << 32);
            g_pri[(size_t)(b * NNODES + n) * CO4 + tid] = v;
        }
    }
}

// ---------------- zero s ----------------
__global__ void k_zero_s() {
    int i = blockIdx.x * 256 + threadIdx.x;
    if (i < NB * CO_TIMES_OD) g_s[i] = 0.f;
}

// ---------------- iter0: s = sum_n priors ----------------
__global__ void k_reduce0() {
    int b = blockIdx.y, n0 = blockIdx.x * 27, tid = threadIdx.x;
    if (tid >= CO4) return;
    float4 acc = make_float4(0.f, 0.f, 0.f, 0.f);
    const ull* p = &g_pri[(size_t)(b * NNODES + n0) * CO4 + tid];
    for (int nn = 0; nn < 27; nn++) {
        float4 q = unpk(p[(size_t)nn * CO4]);
        acc.x += q.x; acc.y += q.y; acc.z += q.z; acc.w += q.w;
    }
    float* sp = &g_s[b * CO_TIMES_OD + tid * 4];
    atomicAdd(sp + 0, acc.x); atomicAdd(sp + 1, acc.y);
    atomicAdd(sp + 2, acc.z); atomicAdd(sp + 3, acc.w);
}

// ---------------- squash s -> caps0 / capsum; resets s ----------------
__global__ void k_squash_out(float scale, int mode) {
    int idx = blockIdx.x * 256 + threadIdx.x;
    if (idx >= NB * NC) return;
    float v[16]; float sn = 0.f;
#pragma unroll
    for (int o = 0; o < 16; o++) { v[o] = g_s[idx * 16 + o] * scale; sn = fmaf(v[o], v[o], sn); }
    float f = sqrtf(sn) / (1.f + sn);
#pragma unroll
    for (int o = 0; o < 16; o++) {
        float cap = v[o] * f;
        if (mode == 0) g_caps0[idx * 16 + o] = cap;
        else           g_capsum[idx * 16 + o] = g_caps0[idx * 16 + o] + cap;
        g_s[idx * 16 + o] = 0.f;
    }
}

// ---------------- routing iteration ----------------
__global__ __launch_bounds__(256) void k_iter(int sel) {
    int b = blockIdx.y;
    int wid = threadIdx.x >> 5;
    int lane = threadIdx.x & 31;
    int nbase = blockIdx.x * 81;
    int c1 = lane;
    bool has2 = lane < (NC - 32);
    int c2 = lane + 32;

    __shared__ float s_acc[CO_TIMES_OD];
    for (int i = threadIdx.x; i < CO_TIMES_OD; i += 256) s_acc[i] = 0.f;

    const float* cb = sel ? &g_capsum[b * CO_TIMES_OD] : &g_caps0[b * CO_TIMES_OD];
    float cap1[16], cap2[16];
#pragma unroll
    for (int o = 0; o < 16; o++) cap1[o] = cb[c1 * OD + o];
#pragma unroll
    for (int o = 0; o < 16; o++) cap2[o] = has2 ? cb[c2 * OD + o] : 0.f;

    float acc1[16], acc2[16];
#pragma unroll
    for (int o = 0; o < 16; o++) { acc1[o] = 0.f; acc2[o] = 0.f; }
    __syncthreads();

    for (int nn = wid; nn < 81; nn += 8) {
        int n = nbase + nn;
        const ull* pp = &g_pri[((size_t)b * NNODES + n) * CO4];
        float pr1[16], pr2[16];
        {
            ulonglong2 q0 = *(const ulonglong2*)(pp + 4 * c1);
            ulonglong2 q1 = *(const ulonglong2*)(pp + 4 * c1 + 2);
            float4 a0 = unpk(q0.x), a1 = unpk(q0.y), a2 = unpk(q1.x), a3 = unpk(q1.y);
            pr1[0]=a0.x; pr1[1]=a0.y; pr1[2]=a0.z; pr1[3]=a0.w;
            pr1[4]=a1.x; pr1[5]=a1.y; pr1[6]=a1.z; pr1[7]=a1.w;
            pr1[8]=a2.x; pr1[9]=a2.y; pr1[10]=a2.z; pr1[11]=a2.w;
            pr1[12]=a3.x; pr1[13]=a3.y; pr1[14]=a3.z; pr1[15]=a3.w;
        }
        if (has2) {
            ulonglong2 q0 = *(const ulonglong2*)(pp + 4 * c2);
            ulonglong2 q1 = *(const ulonglong2*)(pp + 4 * c2 + 2);
            float4 a0 = unpk(q0.x), a1 = unpk(q0.y), a2 = unpk(q1.x), a3 = unpk(q1.y);
            pr2[0]=a0.x; pr2[1]=a0.y; pr2[2]=a0.z; pr2[3]=a0.w;
            pr2[4]=a1.x; pr2[5]=a1.y; pr2[6]=a1.z; pr2[7]=a1.w;
            pr2[8]=a2.x; pr2[9]=a2.y; pr2[10]=a2.z; pr2[11]=a2.w;
            pr2[12]=a3.x; pr2[13]=a3.y; pr2[14]=a3.z; pr2[15]=a3.w;
        } else {
#pragma unroll
            for (int o = 0; o < 16; o++) pr2[o] = 0.f;
        }
        float l1 = 0.f, l2 = 0.f;
#pragma unroll
        for (int o = 0; o < 16; o++) { l1 = fmaf(pr1[o], cap1[o], l1); l2 = fmaf(pr2[o], cap2[o], l2); }

        float e1 = __expf(l1);
        float e2 = has2 ? __expf(l2) : 0.f;
        float ss = e1 + e2;
#pragma unroll
        for (int off = 16; off; off >>= 1) ss += __shfl_xor_sync(0xffffffffu, ss, off);
        float inv = 1.f / ss;
        float p1 = e1 * inv, p2 = e2 * inv;
#pragma unroll
        for (int o = 0; o < 16; o++) { acc1[o] = fmaf(p1, pr1[o], acc1[o]); acc2[o] = fmaf(p2, pr2[o], acc2[o]); }
    }
#pragma unroll
    for (int o = 0; o < 16; o++) atomicAdd(&s_acc[c1 * OD + o], acc1[o]);
    if (has2) {
#pragma unroll
        for (int o = 0; o < 16; o++) atomicAdd(&s_acc[c2 * OD + o], acc2[o]);
    }
    __syncthreads();
    if (threadIdx.x < CO4) {
        float4 a = *(const float4*)&s_acc[threadIdx.x * 4];
        float* sp = &g_s[b * CO_TIMES_OD + threadIdx.x * 4];
        atomicAdd(sp + 0, a.x); atomicAdd(sp + 1, a.y);
        atomicAdd(sp + 2, a.z); atomicAdd(sp + 3, a.w);
    }
}

// ---------------- final ----------------
__global__ void k_final(float* __restrict__ out) {
    int idx = blockIdx.x * 256 + threadIdx.x;
    if (idx >= NB * NC) return;
    float sn = 0.f;
#pragma unroll
    for (int o = 0; o < 16; o++) { float v = g_s[idx * 16 + o]; sn = fmaf(v, v, sn); }
    out[idx] = sn / (1.f + sn);
}

// ---------------- launch ----------------
extern "C" void kernel_launch(void* const* d_in, const int* in_sizes, int n_in,
                              void* d_out, int out_size) {
    const float* x  = (const float*)d_in[0];
    const float* w1 = (const float*)d_in[1];
    const float* b1 = (const float*)d_in[2];
    const float* w2 = (const float*)d_in[3];
    const float* b2 = (const float*)d_in[4];
    const float* rw = (const float*)d_in[5];
    float* out = (float*)d_out;

    k_tr1<<<243, 256>>>(w1);
    k_wpk<<<8192, 256>>>(w2);
    k_conv1<<<dim3(24, 32), 256>>>(x, b1);
    k_zero_up<<<(NB * NNODES * 8 + 255) / 256, 256>>>();
    k_prim<<<dim3(9, 8, 4), 256>>>();
    k_squash_u<<<(NB * NNODES + 255) / 256, 256>>>(b2);
    k_priors<<<dim3(NNODES, 2), 192>>>(rw);

    // iter 0: uniform probs (1/43 folded into squash scale) -> caps0
    k_zero_s<<<172, 256>>>();
    k_reduce0<<<dim3(48, NB), 192>>>();
    k_squash_out<<<11, 256>>>(1.f / 43.f, 0);

    // iter 1: softmax(pr . caps0) -> s -> capsum = caps0 + squash(s)
    k_iter<<<dim3(16, NB), 256>>>(0);
    k_squash_out<<<11, 256>>>(1.f, 1);

    // iter 2: softmax(pr . capsum) -> s -> scores
    k_iter<<<dim3(16, NB), 256>>>(1);
    k_final<<<11, 256>>>(out);
}

// round 13
// speedup vs baseline: 1.6413x; 1.0506x over previous
#include <cuda_runtime.h>
#include <cuda_fp16.h>
#include <math.h>

typedef unsigned long long ull;
typedef unsigned int u32;
typedef unsigned short u16;

// ---------------- problem constants ----------------
#define NB       64
#define NNODES   1296        // 16*81
#define NC       43
#define OD       16
#define CO_TIMES_OD 688      // 43*16
#define CO4      172         // 688/4

#define CPASYNC16(dst_u32, src_ptr) \
    asm volatile("cp.async.cg.shared.global [%0], [%1], 16;" :: "r"(dst_u32), "l"(src_ptr))
#define CPCOMMIT()  asm volatile("cp.async.commit_group;" ::: "memory")
#define CPWAIT0()   asm volatile("cp.async.wait_group 0;" ::: "memory")

// fp16 mma: C[16x8] += A[16x16] * B[16x8], fp32 accum
#define MMA(d, A, b0, b1) \
    asm volatile("mma.sync.aligned.m16n8k16.row.col.f32.f16.f16.f32 " \
                 "{%0,%1,%2,%3},{%4,%5,%6,%7},{%8,%9},{%0,%1,%2,%3};" \
                 : "+f"(d[0]), "+f"(d[1]), "+f"(d[2]), "+f"(d[3]) \
                 : "r"(A[0]), "r"(A[1]), "r"(A[2]), "r"(A[3]), "r"(b0), "r"(b1))

static __device__ __forceinline__ u16 h16(float v){ return __half_as_ushort(__float2half_rn(v)); }

// ---------------- device scratch ----------------
__device__ u32    g_w1pk[65536];                   // conv1 weights fp16 hi/lo, mma A-fragment packed
__device__ u32    g_wpk[2097152];                  // prim weights fp16 hi/lo, mma A-fragment packed
__device__ u16    g_hb[9437184];                   // conv1 out fp16: [b][ci][y24][x24]
__device__ float  g_up[NB * NNODES * 8];           // pre-squash primary caps (atomic accum)
__device__ float  g_u[NB * NNODES * 8];            // squashed primary capsules
__device__ ull    g_pri[(size_t)NB * NNODES * CO4];// priors, fp16x4 packed (114MB)
__device__ float  g_s[NB * CO_TIMES_OD];
__device__ float  g_caps0[NB * CO_TIMES_OD];
__device__ float  g_capsum[NB * CO_TIMES_OD];

static __device__ __forceinline__ unsigned h2u(__half2 h){ return *reinterpret_cast<unsigned*>(&h); }
static __device__ __forceinline__ __half2 u2h(unsigned u){ return *reinterpret_cast<__half2*>(&u); }

static __device__ __forceinline__ float4 unpk(ull v) {
    float2 a = __half22float2(u2h((unsigned)v));
    float2 b = __half22float2(u2h((unsigned)(v >> 32)));
    return make_float4(a.x, a.y, b.x, b.y);
}

// ---------------- conv1 weights -> fp16 hi/lo, mma A-fragment order ----------------
// idx = ((pl*16+mb)*16+kf)*128 + lane*4 + r
// co = mb*16 + (lane>>2) + (r&1)*8 ; k = kf*16 + (lane&3)*2 + (r>>1)*8  (k native ci*81+ky*9+kx, pad->0)
__global__ void k_wpk1(const float* __restrict__ w) {
    int idx = blockIdx.x * 256 + threadIdx.x;      // 65,536 exact
    int r = idx & 3, lane = (idx >> 2) & 31, kf = (idx >> 7) & 15, mb = (idx >> 11) & 15, pl = idx >> 15;
    int co = mb * 16 + (lane >> 2) + (r & 1) * 8;
    int k  = kf * 16 + (lane & 3) * 2 + (r >> 1) * 8;
    float v0 = (k < 243)     ? w[co * 243 + k]     : 0.f;
    float v1 = (k + 1 < 243) ? w[co * 243 + k + 1] : 0.f;
    if (pl) {
        v0 -= __half2float(__float2half_rn(v0));
        v1 -= __half2float(__float2half_rn(v1));
    }
    g_w1pk[idx] = (u32)h16(v0) | ((u32)h16(v1) << 16);
}

// ---------------- prim weights -> fp16 hi/lo, mma A-fragment order ----------------
__global__ void k_wpk(const float* __restrict__ w) {
    int idx = blockIdx.x * 256 + threadIdx.x;      // 2,097,152 exact
    int r = idx & 3, lane = (idx >> 2) & 31, ks = (idx >> 7) & 1023;
    int cb = (idx >> 17) & 7, pl = idx >> 20;
    int row = cb * 16 + (lane >> 2) + (r & 1) * 8;
    int kk  = ks * 16 + (lane & 3) * 2 + (r >> 1) * 8;
    float v0 = w[row * 16384 + kk];
    float v1 = w[row * 16384 + kk + 1];
    if (pl) {
        v0 -= __half2float(__float2half_rn(v0));
        v1 -= __half2float(__float2half_rn(v1));
    }
    g_wpk[idx] = (u32)h16(v0) | ((u32)h16(v1) << 16);
}

// ---------------- conv1 via mma.sync fp16 3-term split ----------------
// GEMM per block: C[co 128][n 96] += W1[co][k 256] * X[k][n], n = (j 4 batches, ox 24)
// grid (24 oy, 16 bg, 2 z), 256 threads = 8 warps, warp owns a 16-co slice, all 96 n
__global__ __launch_bounds__(256, 2) void k_conv1(const float* __restrict__ x,
                                                  const float* __restrict__ bias) {
    int oy = blockIdx.x, bg = blockIdx.y, z = blockIdx.z;
    int tid = threadIdx.x, lane = tid & 31, warp = tid >> 5;
    __shared__ float xraw[4 * 864];      // [j][ci*288 + r*32 + col]
    __shared__ int   kmap[64];
    __shared__ u16   Bs[2][96 * 72];     // [plane][n][k-chunk 64, stride 72 -> conflict-free frags]

    // stage x for 4 batches (coalesced)
    for (int i = tid; i < 3456; i += 256) {
        int j = i / 864, off = i - j * 864;
        int ci = off / 288, rem = off - ci * 288;
        int r = rem >> 5, col = rem & 31;
        xraw[i] = x[((bg * 4 + j) * 3 + ci) * 1024 + (oy + r) * 32 + col];
    }

    float acc[12][4];
#pragma unroll
    for (int a = 0; a < 12; a++)
#pragma unroll
        for (int e = 0; e < 4; e++) acc[a][e] = 0.f;

#pragma unroll 1
    for (int kc = 0; kc < 4; kc++) {
        __syncthreads();
        if (tid < 64) {
            int k = kc * 64 + tid;
            int m = -1;
            if (k < 243) {
                int ci = k / 81, rem = k - ci * 81;
                int ky = rem / 9, kx = rem - ky * 9;
                m = ci * 288 + ky * 32 + kx;
            }
            kmap[tid] = m;
        }
        __syncthreads();
        // build B tile (im2col) for this k-chunk, both planes
        for (int i = tid; i < 6144; i += 256) {
            int kk = i & 63, n = i >> 6;
            int j = n / 24, ox = n - j * 24;
            int m = kmap[kk];
            float v = (m >= 0) ? xraw[j * 864 + m + ox] : 0.f;
            __half hh = __float2half_rn(v);
            Bs[0][n * 72 + kk] = __half_as_ushort(hh);
            Bs[1][n * 72 + kk] = h16(v - __half2float(hh));
        }
        __syncthreads();
        int mb = z * 8 + warp;
#pragma unroll
        for (int kfl = 0; kfl < 4; kfl++) {
            int kf = kc * 4 + kfl;
            u32 Ah[4], Al[4];
            {
                uint4 q = ((const uint4*)(g_w1pk + (size_t)((0 * 16 + mb) * 16 + kf) * 128))[lane];
                Ah[0] = q.x; Ah[1] = q.y; Ah[2] = q.z; Ah[3] = q.w;
            }
            {
                uint4 q = ((const uint4*)(g_w1pk + (size_t)((1 * 16 + mb) * 16 + kf) * 128))[lane];
                Al[0] = q.x; Al[1] = q.y; Al[2] = q.z; Al[3] = q.w;
            }
#pragma unroll
            for (int nf = 0; nf < 12; nf++) {
                const u16* bp = &Bs[0][(nf * 8 + (lane >> 2)) * 72 + kfl * 16 + (lane & 3) * 2];
                u32 bh0 = *(const u32*)bp;
                u32 bh1 = *(const u32*)(bp + 8);
                const u16* bq = bp + 96 * 72;
                u32 bl0 = *(const u32*)bq;
                u32 bl1 = *(const u32*)(bq + 8);
                MMA(acc[nf], Ah, bh0, bh1);   // Wh * Xh
                MMA(acc[nf], Ah, bl0, bl1);   // Wh * Xl
                MMA(acc[nf], Al, bh0, bh1);   // Wl * Xh
            }
        }
    }

    // epilogue: bias + relu + fp16 store
    int row = lane >> 2;
    int co0 = z * 128 + warp * 16 + row;
    float bv0 = bias[co0], bv1 = bias[co0 + 8];
#pragma unroll
    for (int nf = 0; nf < 12; nf++) {
        int n = nf * 8 + (lane & 3) * 2;
        int j = n / 24, ox = n - j * 24;
        int b = bg * 4 + j;
#pragma unroll
        for (int hl = 0; hl < 2; hl++) {
            int co = co0 + hl * 8;
            float bv = hl ? bv1 : bv0;
            float v0 = fmaxf(acc[nf][hl * 2 + 0] + bv, 0.f);
            float v1 = fmaxf(acc[nf][hl * 2 + 1] + bv, 0.f);
            u32 pk = (u32)h16(v0) | ((u32)h16(v1) << 16);
            *(u32*)&g_hb[(b * 256 + co) * 576 + oy * 24 + ox] = pk;
        }
    }
}

// ---------------- zero pre-squash buffer ----------------
__global__ void k_zero_up() {
    int i = blockIdx.x * 256 + threadIdx.x;
    if (i < NB * NNODES * 8) g_up[i] = 0.f;
}

// ---------------- prim conv via mma.sync fp16 weight-split (2 terms) ----------------
__global__ __launch_bounds__(256) void k_prim() {
    int oy = blockIdx.x, bg = blockIdx.y, z = blockIdx.z;
    int tid = threadIdx.x, lane = tid & 31, warp = tid >> 5;
    int warp_m = warp & 3, warp_n = warp >> 2;
    __shared__ u16 sbm[2][2048];       // [buf][j 8][ky 8][32 cols]
    u32 sb0 = (u32)__cvta_generic_to_shared(&sbm[0][0]);

    if (tid < 128) {
        int buf = tid >> 6, rowi = tid & 63;
        *(uint4*)&sbm[buf][rowi * 32 + 24] = make_uint4(0, 0, 0, 0);
    }

    int cB[5];
#pragma unroll
    for (int nf = 0; nf < 5; nf++) {
        int n = warp_n * 40 + nf * 8 + (lane >> 2);
        int j = n / 10, ox = n - j * 10;
        cB[nf] = j * 256 + 2 * ox + (lane & 3) * 2;
    }

    float acc[2][5][4];
#pragma unroll
    for (int a = 0; a < 2; a++)
#pragma unroll
        for (int b = 0; b < 5; b++)
#pragma unroll
            for (int c = 0; c < 4; c++) acc[a][b][c] = 0.f;

    int ci0 = z * 64;
    if (tid < 192) {
        int seg = tid % 3, t = tid / 3;
        int ky = t & 7, j = t >> 3;
        const u16* src = &g_hb[((size_t)((bg * 8 + j) * 256 + ci0)) * 576 + (2 * oy + ky) * 24 + seg * 8];
        u32 dst = sb0 + (u32)(((j * 8 + ky) * 32 + seg * 8) * 2);
        CPASYNC16(dst, src);
    }
    CPCOMMIT(); CPWAIT0();
    __syncthreads();

#pragma unroll 1
    for (int cc = 0; cc < 64; cc++) {
        if (cc < 63) {
            int nb = (cc + 1) & 1;
            int ci = ci0 + cc + 1;
            if (tid < 192) {
                int seg = tid % 3, t = tid / 3;
                int ky = t & 7, j = t >> 3;
                const u16* src = &g_hb[((size_t)((bg * 8 + j) * 256 + ci)) * 576 + (2 * oy + ky) * 24 + seg * 8];
                u32 dst = sb0 + (u32)(nb * 4096 + ((j * 8 + ky) * 32 + seg * 8) * 2);
                CPASYNC16(dst, src);
            }
            CPCOMMIT();
        }
        const u16* sbuf = &sbm[cc & 1][0];
#pragma unroll
        for (int ks = 0; ks < 4; ks++) {
            int ksg = (ci0 + cc) * 4 + ks;
            u32 A[2][2][4];
#pragma unroll
            for (int pl = 0; pl < 2; pl++)
#pragma unroll
                for (int mf = 0; mf < 2; mf++) {
                    const uint4* ap = (const uint4*)(g_wpk + (size_t)((pl * 8 + warp_m * 2 + mf) * 1024 + ksg) * 128);
                    uint4 q = ap[lane];
                    A[pl][mf][0] = q.x; A[pl][mf][1] = q.y; A[pl][mf][2] = q.z; A[pl][mf][3] = q.w;
                }
#pragma unroll
            for (int nf = 0; nf < 5; nf++) {
                u32 b0 = *(const u32*)&sbuf[cB[nf] + (2 * ks) * 32];
                u32 b1 = *(const u32*)&sbuf[cB[nf] + (2 * ks + 1) * 32];
#pragma unroll
                for (int mf = 0; mf < 2; mf++) {
                    MMA(acc[mf][nf], A[0][mf], b0, b1);   // W_hi * X
                    MMA(acc[mf][nf], A[1][mf], b0, b1);   // W_lo * X
                }
            }
        }
        if (cc < 63) {
            CPWAIT0();
            __syncthreads();
        }
    }

#pragma unroll
    for (int mf = 0; mf < 2; mf++)
#pragma unroll
        for (int nf = 0; nf < 5; nf++)
#pragma unroll
            for (int e = 0; e < 4; e++) {
                int co = warp_m * 32 + mf * 16 + (lane >> 2) + (e >> 1) * 8;
                int n = warp_n * 40 + nf * 8 + (lane & 3) * 2 + (e & 1);
                int j = n / 10, ox = n - j * 10;
                if (ox < 9) {
                    int b = bg * 8 + j;
                    int node = (co & 15) * 81 + oy * 9 + ox;
                    atomicAdd(&g_up[((size_t)b * NNODES + node) * 8 + (co >> 4)], acc[mf][nf][e]);
                }
            }
}

// ---------------- squash primary capsules (adds bias) ----------------
__global__ void k_squash_u(const float* __restrict__ bias) {
    int idx = blockIdx.x * 256 + threadIdx.x;
    if (idx >= NB * NNODES) return;
    int n = idx % NNODES;
    int g2 = n / 81;
    float v[8]; float sn = 0.f;
#pragma unroll
    for (int i = 0; i < 8; i++) {
        v[i] = g_up[idx * 8 + i] + bias[i * 16 + g2];
        sn = fmaf(v[i], v[i], sn);
    }
    float f = sqrtf(sn) / (1.f + sn);
#pragma unroll
    for (int i = 0; i < 8; i++) g_u[idx * 8 + i] = v[i] * f;
}

// ---------------- priors[b,n,c,o] = sum_i u[b,n,i] * W[n,c,i,o]; store fp16x4 ----------------
__global__ __launch_bounds__(192) void k_priors(const float* __restrict__ route_w) {
    int n = blockIdx.x, by = blockIdx.y, tid = threadIdx.x;
    __shared__ float rw[NC * 8 * OD];
    __shared__ float us[32 * 8];
    for (int idx = tid; idx < 5504; idx += 192) rw[idx] = route_w[n * 5504 + idx];
    for (int idx = tid; idx < 256; idx += 192) {
        int b = (idx >> 3) + by * 32, i = idx & 7;
        us[idx] = g_u[(b * NNODES + n) * 8 + i];
    }
    __syncthreads();
    if (tid < CO4) {
        int c = tid >> 2;
        int obase = (tid & 3) * 4;
        const float* rwc = &rw[c * 128 + obase];
        for (int bl = 0; bl < 32; bl++) {
            int b = by * 32 + bl;
            const float* ub = &us[bl * 8];
            float4 sum = make_float4(0.f, 0.f, 0.f, 0.f);
#pragma unroll
            for (int i = 0; i < 8; i++) {
                float u = ub[i];
                sum.x = fmaf(u, rwc[i * 16 + 0], sum.x);
                sum.y = fmaf(u, rwc[i * 16 + 1], sum.y);
                sum.z = fmaf(u, rwc[i * 16 + 2], sum.z);
                sum.w = fmaf(u, rwc[i * 16 + 3], sum.w);
            }
            __half2 p01 = __floats2half2_rn(sum.x, sum.y);
            __half2 p23 = __floats2half2_rn(sum.z, sum.w);
            ull v = (ull)h2u(p01) | ((ull)h2u(p23) << 32);
            g_pri[(size_t)(b * NNODES + n) * CO4 + tid] = v;
        }
    }
}

// ---------------- zero s ----------------
__global__ void k_zero_s() {
    int i = blockIdx.x * 256 + threadIdx.x;
    if (i < NB * CO_TIMES_OD) g_s[i] = 0.f;
}

// ---------------- iter0: s = sum_n priors ----------------
__global__ void k_reduce0() {
    int b = blockIdx.y, n0 = blockIdx.x * 27, tid = threadIdx.x;
    if (tid >= CO4) return;
    float4 acc = make_float4(0.f, 0.f, 0.f, 0.f);
    const ull* p = &g_pri[(size_t)(b * NNODES + n0) * CO4 + tid];
    for (int nn = 0; nn < 27; nn++) {
        float4 q = unpk(p[(size_t)nn * CO4]);
        acc.x += q.x; acc.y += q.y; acc.z += q.z; acc.w += q.w;
    }
    float* sp = &g_s[b * CO_TIMES_OD + tid * 4];
    atomicAdd(sp + 0, acc.x); atomicAdd(sp + 1, acc.y);
    atomicAdd(sp + 2, acc.z); atomicAdd(sp + 3, acc.w);
}

// ---------------- squash s -> caps0 / capsum; resets s ----------------
__global__ void k_squash_out(float scale, int mode) {
    int idx = blockIdx.x * 256 + threadIdx.x;
    if (idx >= NB * NC) return;
    float v[16]; float sn = 0.f;
#pragma unroll
    for (int o = 0; o < 16; o++) { v[o] = g_s[idx * 16 + o] * scale; sn = fmaf(v[o], v[o], sn); }
    float f = sqrtf(sn) / (1.f + sn);
#pragma unroll
    for (int o = 0; o < 16; o++) {
        float cap = v[o] * f;
        if (mode == 0) g_caps0[idx * 16 + o] = cap;
        else           g_capsum[idx * 16 + o] = g_caps0[idx * 16 + o] + cap;
        g_s[idx * 16 + o] = 0.f;
    }
}

// ---------------- routing iteration ----------------
__global__ __launch_bounds__(256) void k_iter(int sel) {
    int b = blockIdx.y;
    int wid = threadIdx.x >> 5;
    int lane = threadIdx.x & 31;
    int nbase = blockIdx.x * 81;
    int c1 = lane;
    bool has2 = lane < (NC - 32);
    int c2 = lane + 32;

    __shared__ float s_acc[CO_TIMES_OD];
    for (int i = threadIdx.x; i < CO_TIMES_OD; i += 256) s_acc[i] = 0.f;

    const float* cb = sel ? &g_capsum[b * CO_TIMES_OD] : &g_caps0[b * CO_TIMES_OD];
    float cap1[16], cap2[16];
#pragma unroll
    for (int o = 0; o < 16; o++) cap1[o] = cb[c1 * OD + o];
#pragma unroll
    for (int o = 0; o < 16; o++) cap2[o] = has2 ? cb[c2 * OD + o] : 0.f;

    float acc1[16], acc2[16];
#pragma unroll
    for (int o = 0; o < 16; o++) { acc1[o] = 0.f; acc2[o] = 0.f; }
    __syncthreads();

    for (int nn = wid; nn < 81; nn += 8) {
        int n = nbase + nn;
        const ull* pp = &g_pri[((size_t)b * NNODES + n) * CO4];
        float pr1[16], pr2[16];
        {
            ulonglong2 q0 = *(const ulonglong2*)(pp + 4 * c1);
            ulonglong2 q1 = *(const ulonglong2*)(pp + 4 * c1 + 2);
            float4 a0 = unpk(q0.x), a1 = unpk(q0.y), a2 = unpk(q1.x), a3 = unpk(q1.y);
            pr1[0]=a0.x; pr1[1]=a0.y; pr1[2]=a0.z; pr1[3]=a0.w;
            pr1[4]=a1.x; pr1[5]=a1.y; pr1[6]=a1.z; pr1[7]=a1.w;
            pr1[8]=a2.x; pr1[9]=a2.y; pr1[10]=a2.z; pr1[11]=a2.w;
            pr1[12]=a3.x; pr1[13]=a3.y; pr1[14]=a3.z; pr1[15]=a3.w;
        }
        if (has2) {
            ulonglong2 q0 = *(const ulonglong2*)(pp + 4 * c2);
            ulonglong2 q1 = *(const ulonglong2*)(pp + 4 * c2 + 2);
            float4 a0 = unpk(q0.x), a1 = unpk(q0.y), a2 = unpk(q1.x), a3 = unpk(q1.y);
            pr2[0]=a0.x; pr2[1]=a0.y; pr2[2]=a0.z; pr2[3]=a0.w;
            pr2[4]=a1.x; pr2[5]=a1.y; pr2[6]=a1.z; pr2[7]=a1.w;
            pr2[8]=a2.x; pr2[9]=a2.y; pr2[10]=a2.z; pr2[11]=a2.w;
            pr2[12]=a3.x; pr2[13]=a3.y; pr2[14]=a3.z; pr2[15]=a3.w;
        } else {
#pragma unroll
            for (int o = 0; o < 16; o++) pr2[o] = 0.f;
        }
        float l1 = 0.f, l2 = 0.f;
#pragma unroll
        for (int o = 0; o < 16; o++) { l1 = fmaf(pr1[o], cap1[o], l1); l2 = fmaf(pr2[o], cap2[o], l2); }

        float e1 = __expf(l1);
        float e2 = has2 ? __expf(l2) : 0.f;
        float ss = e1 + e2;
#pragma unroll
        for (int off = 16; off; off >>= 1) ss += __shfl_xor_sync(0xffffffffu, ss, off);
        float inv = 1.f / ss;
        float p1 = e1 * inv, p2 = e2 * inv;
#pragma unroll
        for (int o = 0; o < 16; o++) { acc1[o] = fmaf(p1, pr1[o], acc1[o]); acc2[o] = fmaf(p2, pr2[o], acc2[o]); }
    }
#pragma unroll
    for (int o = 0; o < 16; o++) atomicAdd(&s_acc[c1 * OD + o], acc1[o]);
    if (has2) {
#pragma unroll
        for (int o = 0; o < 16; o++) atomicAdd(&s_acc[c2 * OD + o], acc2[o]);
    }
    __syncthreads();
    if (threadIdx.x < CO4) {
        float4 a = *(const float4*)&s_acc[threadIdx.x * 4];
        float* sp = &g_s[b * CO_TIMES_OD + threadIdx.x * 4];
        atomicAdd(sp + 0, a.x); atomicAdd(sp + 1, a.y);
        atomicAdd(sp + 2, a.z); atomicAdd(sp + 3, a.w);
    }
}

// ---------------- final ----------------
__global__ void k_final(float* __restrict__ out) {
    int idx = blockIdx.x * 256 + threadIdx.x;
    if (idx >= NB * NC) return;
    float sn = 0.f;
#pragma unroll
    for (int o = 0; o < 16; o++) { float v = g_s[idx * 16 + o]; sn = fmaf(v, v, sn); }
    out[idx] = sn / (1.f + sn);
}

// ---------------- launch ----------------
extern "C" void kernel_launch(void* const* d_in, const int* in_sizes, int n_in,
                              void* d_out, int out_size) {
    const float* x  = (const float*)d_in[0];
    const float* w1 = (const float*)d_in[1];
    const float* b1 = (const float*)d_in[2];
    const float* w2 = (const float*)d_in[3];
    const float* b2 = (const float*)d_in[4];
    const float* rw = (const float*)d_in[5];
    float* out = (float*)d_out;

    k_wpk1<<<256, 256>>>(w1);
    k_wpk<<<8192, 256>>>(w2);
    k_conv1<<<dim3(24, 16, 2), 256>>>(x, b1);
    k_zero_up<<<(NB * NNODES * 8 + 255) / 256, 256>>>();
    k_prim<<<dim3(9, 8, 4), 256>>>();
    k_squash_u<<<(NB * NNODES + 255) / 256, 256>>>(b2);
    k_priors<<<dim3(NNODES, 2), 192>>>(rw);

    // iter 0: uniform probs (1/43 folded into squash scale) -> caps0
    k_zero_s<<<172, 256>>>();
    k_reduce0<<<dim3(48, NB), 192>>>();
    k_squash_out<<<11, 256>>>(1.f / 43.f, 0);

    // iter 1: softmax(pr . caps0) -> s -> capsum = caps0 + squash(s)
    k_iter<<<dim3(16, NB), 256>>>(0);
    k_squash_out<<<11, 256>>>(1.f, 1);

    // iter 2: softmax(pr . capsum) -> s -> scores
    k_iter<<<dim3(16, NB), 256>>>(1);
    k_final<<<11, 256>>>(out);
}